// round 2
// baseline (speedup 1.0000x reference)
#include <cuda_runtime.h>
#include <math.h>

#define BATCH 4
#define SEQ   4096
#define DIN   256
#define HID   128

// ---------------- scratch (no cudaMalloc allowed) ----------------
__device__ float g_q[BATCH * SEQ * HID];
__device__ float g_k[BATCH * SEQ * HID];
__device__ float g_v[BATCH * SEQ * HID];

// =================================================================
// QKV projection: out[m][h] = sum_k x[m][k] * W[k][h] + b[h]
// M = BATCH*SEQ = 16384, K = 256, H = 128.
// Block 256 threads (16x16), tile 64x64, TK = 16.
// =================================================================
__global__ void __launch_bounds__(256)
proj_kernel(const float* __restrict__ x, const float* __restrict__ W,
            const float* __restrict__ bias, float* __restrict__ out)
{
    __shared__ float xs[16][68];   // [k][m] transposed
    __shared__ float ws[16][68];   // [k][h]

    const int tid = threadIdx.x;
    const int ty  = tid >> 4;      // 0..15 (row group)
    const int tx  = tid & 15;      // 0..15 (col group)
    const int m0  = blockIdx.x * 64;
    const int h0  = blockIdx.y * 64;

    float acc[4][4] = {};

    for (int k0 = 0; k0 < DIN; k0 += 16) {
        // x tile: thread (k = tid%16, r = tid/16), rows stride 16
        {
            const int k = tid & 15;
            const int r = tid >> 4;
            #pragma unroll
            for (int i = 0; i < 4; i++)
                xs[k][r + 16 * i] = x[(size_t)(m0 + r + 16 * i) * DIN + (k0 + k)];
        }
        // W tile: thread (c = tid%64, kr = tid/64), k stride 4
        {
            const int c  = tid & 63;
            const int kr = tid >> 6;
            #pragma unroll
            for (int i = 0; i < 4; i++)
                ws[kr + 4 * i][c] = W[(size_t)(k0 + kr + 4 * i) * HID + (h0 + c)];
        }
        __syncthreads();

        #pragma unroll
        for (int kk = 0; kk < 16; kk++) {
            const float4 a4 = *(const float4*)&xs[kk][ty * 4];
            const float4 b4 = *(const float4*)&ws[kk][tx * 4];
            const float av[4] = {a4.x, a4.y, a4.z, a4.w};
            const float bv[4] = {b4.x, b4.y, b4.z, b4.w};
            #pragma unroll
            for (int a = 0; a < 4; a++)
                #pragma unroll
                for (int b = 0; b < 4; b++)
                    acc[a][b] += av[a] * bv[b];
        }
        __syncthreads();
    }

    #pragma unroll
    for (int a = 0; a < 4; a++) {
        const int row = m0 + ty * 4 + a;
        float4 o;
        o.x = acc[a][0] + bias[h0 + tx * 4 + 0];
        o.y = acc[a][1] + bias[h0 + tx * 4 + 1];
        o.z = acc[a][2] + bias[h0 + tx * 4 + 2];
        o.w = acc[a][3] + bias[h0 + tx * 4 + 3];
        *(float4*)&out[(size_t)row * HID + h0 + tx * 4] = o;
    }
}

// =================================================================
// Fused flash attention (no 1/sqrt(d) scaling, faithful to ref).
// Grid (SEQ/BQ = 32, BATCH = 4) = 128 blocks, 512 threads.
// BQ = 128 queries/block, BK = 64 keys/tile, online softmax.
// Q,K in smem d-major (transposed) for float4 inner loop;
// strides chosen so STS.128 transpose writes are bank-conflict-free
// (stride % 32-in-float4-banks pattern = 4d mod 32).
// =================================================================
#define BQ 128
#define BK 64
#define ATH 512
#define QS_STRIDE 132   // BQ + 4
#define KS_STRIDE 68    // BK + 4
#define PS_STRIDE 68    // BK + 4
#define LOG2E 1.4426950408889634f

#define SMEM_FLOATS (HID * QS_STRIDE + HID * KS_STRIDE + BK * HID + BQ * PS_STRIDE)

__global__ void __launch_bounds__(ATH, 1)
attn_kernel(const float* __restrict__ Q, const float* __restrict__ K,
            const float* __restrict__ V, float* __restrict__ out)
{
    extern __shared__ float sm[];
    float* Qs = sm;                        // [HID][QS_STRIDE]  (d-major, col = q row)
    float* Ks = Qs + HID * QS_STRIDE;      // [HID][KS_STRIDE]  (d-major, col = k row)
    float* Vs = Ks + HID * KS_STRIDE;      // [BK][HID]         (natural)
    float* Ps = Vs + BK * HID;             // [BQ][PS_STRIDE]

    const int tid = threadIdx.x;
    const int ty  = tid >> 4;              // 0..31  -> 4 query rows each
    const int tx  = tid & 15;              // 0..15  -> 4 key cols / 8 out cols each
    const int b   = blockIdx.y;
    const int q0  = blockIdx.x * BQ;

    const float* Qb = Q + (size_t)b * SEQ * HID;
    const float* Kb = K + (size_t)b * SEQ * HID;
    const float* Vb = V + (size_t)b * SEQ * HID;

    // ---- load Q tile transposed: Qs[d][r] ----
    {
        const int d  = tid & 127;
        const int r0 = (tid >> 7) * 4;     // 0,4,8,12
        #pragma unroll
        for (int base = 0; base < BQ; base += 16) {
            const int r = base + r0;
            float4 t;
            t.x = Qb[(size_t)(q0 + r + 0) * HID + d];
            t.y = Qb[(size_t)(q0 + r + 1) * HID + d];
            t.z = Qb[(size_t)(q0 + r + 2) * HID + d];
            t.w = Qb[(size_t)(q0 + r + 3) * HID + d];
            *(float4*)&Qs[d * QS_STRIDE + r] = t;
        }
    }

    float O[4][8] = {};
    float m_r[4], l_r[4];
    #pragma unroll
    for (int a = 0; a < 4; a++) { m_r[a] = -1e30f; l_r[a] = 0.f; }

    for (int k0 = 0; k0 < SEQ; k0 += BK) {
        __syncthreads();   // previous tile's PV reads of Vs/Ps done

        // ---- load K tile transposed + V tile natural ----
        {
            const int d  = tid & 127;
            const int r0 = (tid >> 7) * 4;
            #pragma unroll
            for (int base = 0; base < BK; base += 16) {
                const int r = base + r0;
                float4 t;
                t.x = Kb[(size_t)(k0 + r + 0) * HID + d];
                t.y = Kb[(size_t)(k0 + r + 1) * HID + d];
                t.z = Kb[(size_t)(k0 + r + 2) * HID + d];
                t.w = Kb[(size_t)(k0 + r + 3) * HID + d];
                *(float4*)&Ks[d * KS_STRIDE + r] = t;
            }
            const int c  = (tid & 31) * 4;
            const int j0 = tid >> 5;       // 0..15
            #pragma unroll
            for (int base = 0; base < BK; base += 16) {
                *(float4*)&Vs[(base + j0) * HID + c] =
                    *(const float4*)&Vb[(size_t)(k0 + base + j0) * HID + c];
            }
        }
        __syncthreads();

        // ---- S = Q K^T  (64x... per-thread 4x4 micro-tile) ----
        float s[4][4] = {};
        #pragma unroll 8
        for (int d = 0; d < HID; d++) {
            const float4 q4 = *(const float4*)&Qs[d * QS_STRIDE + ty * 4];
            const float4 k4 = *(const float4*)&Ks[d * KS_STRIDE + tx * 4];
            const float qv[4] = {q4.x, q4.y, q4.z, q4.w};
            const float kv[4] = {k4.x, k4.y, k4.z, k4.w};
            #pragma unroll
            for (int a = 0; a < 4; a++)
                #pragma unroll
                for (int bb = 0; bb < 4; bb++)
                    s[a][bb] += qv[a] * kv[bb];
        }

        // ---- online softmax (row spread over 16 tx threads) ----
        #pragma unroll
        for (int a = 0; a < 4; a++) {
            float mx = fmaxf(fmaxf(s[a][0], s[a][1]), fmaxf(s[a][2], s[a][3]));
            #pragma unroll
            for (int o = 8; o; o >>= 1)
                mx = fmaxf(mx, __shfl_xor_sync(0xFFFFFFFFu, mx, o, 16));
            const float mnew = fmaxf(m_r[a], mx);
            const float corr = exp2f((m_r[a] - mnew) * LOG2E);
            m_r[a] = mnew;
            float p[4], rs = 0.f;
            #pragma unroll
            for (int bb = 0; bb < 4; bb++) {
                p[bb] = exp2f((s[a][bb] - mnew) * LOG2E);
                rs += p[bb];
            }
            #pragma unroll
            for (int o = 8; o; o >>= 1)
                rs += __shfl_xor_sync(0xFFFFFFFFu, rs, o, 16);
            l_r[a] = l_r[a] * corr + rs;
            #pragma unroll
            for (int c = 0; c < 8; c++) O[a][c] *= corr;
            *(float4*)&Ps[(ty * 4 + a) * PS_STRIDE + tx * 4] =
                make_float4(p[0], p[1], p[2], p[3]);
        }
        __syncthreads();   // Ps visible to all

        // ---- O += P * V ----
        #pragma unroll 4
        for (int j = 0; j < BK; j++) {
            const float4 v0 = *(const float4*)&Vs[j * HID + tx * 8];
            const float4 v1 = *(const float4*)&Vs[j * HID + tx * 8 + 4];
            #pragma unroll
            for (int a = 0; a < 4; a++) {
                const float pa = Ps[(ty * 4 + a) * PS_STRIDE + j];
                O[a][0] += pa * v0.x;  O[a][1] += pa * v0.y;
                O[a][2] += pa * v0.z;  O[a][3] += pa * v0.w;
                O[a][4] += pa * v1.x;  O[a][5] += pa * v1.y;
                O[a][6] += pa * v1.z;  O[a][7] += pa * v1.w;
            }
        }
    }

    // ---- epilogue: out = O / l ----
    #pragma unroll
    for (int a = 0; a < 4; a++) {
        const float inv = 1.0f / l_r[a];
        const int row = q0 + ty * 4 + a;
        float* op = out + ((size_t)b * SEQ + row) * HID + tx * 8;
        float4 o0, o1;
        o0.x = O[a][0] * inv; o0.y = O[a][1] * inv;
        o0.z = O[a][2] * inv; o0.w = O[a][3] * inv;
        o1.x = O[a][4] * inv; o1.y = O[a][5] * inv;
        o1.z = O[a][6] * inv; o1.w = O[a][7] * inv;
        *(float4*)op       = o0;
        *(float4*)(op + 4) = o1;
    }
}

// =================================================================
// launch
// =================================================================
extern "C" void kernel_launch(void* const* d_in, const int* in_sizes, int n_in,
                              void* d_out, int out_size)
{
    (void)in_sizes; (void)n_in; (void)out_size;
    const float* x  = (const float*)d_in[0];
    const float* Wq = (const float*)d_in[1];
    const float* bq = (const float*)d_in[2];
    const float* Wk = (const float*)d_in[3];
    const float* bk = (const float*)d_in[4];
    const float* Wv = (const float*)d_in[5];
    const float* bv = (const float*)d_in[6];
    float* out = (float*)d_out;

    float *q, *k, *v;
    cudaGetSymbolAddress((void**)&q, g_q);
    cudaGetSymbolAddress((void**)&k, g_k);
    cudaGetSymbolAddress((void**)&v, g_v);

    const int smem_bytes = SMEM_FLOATS * (int)sizeof(float);  // 169,984 B
    cudaFuncSetAttribute(attn_kernel,
                         cudaFuncAttributeMaxDynamicSharedMemorySize, smem_bytes);

    dim3 pgrid((BATCH * SEQ) / 64, HID / 64);   // (256, 2)
    proj_kernel<<<pgrid, 256>>>(x, Wq, bq, q);
    proj_kernel<<<pgrid, 256>>>(x, Wk, bk, k);
    proj_kernel<<<pgrid, 256>>>(x, Wv, bv, v);

    dim3 agrid(SEQ / BQ, BATCH);                // (32, 4)
    attn_kernel<<<agrid, ATH, smem_bytes>>>(q, k, v, out);
}

// round 3
// speedup vs baseline: 1.0004x; 1.0004x over previous
#include <cuda_runtime.h>
#include <math.h>

#define BATCH 4
#define SEQ   4096
#define DIN   256
#define HID   128

// ---------------- scratch (no cudaMalloc allowed) ----------------
__device__ float g_q[BATCH * SEQ * HID];
__device__ float g_k[BATCH * SEQ * HID];
__device__ float g_v[BATCH * SEQ * HID];

// =================================================================
// QKV projection: out[m][h] = sum_k x[m][k] * W[k][h] + b[h]
// M = BATCH*SEQ = 16384, K = 256, H = 128.
// Block 256 threads (16x16), tile 64x64, TK = 16.
// =================================================================
__global__ void __launch_bounds__(256)
proj_kernel(const float* __restrict__ x, const float* __restrict__ W,
            const float* __restrict__ bias, float* __restrict__ out)
{
    __shared__ float xs[16][68];   // [k][m] transposed
    __shared__ float ws[16][68];   // [k][h]

    const int tid = threadIdx.x;
    const int ty  = tid >> 4;      // 0..15 (row group)
    const int tx  = tid & 15;      // 0..15 (col group)
    const int m0  = blockIdx.x * 64;
    const int h0  = blockIdx.y * 64;

    float acc[4][4] = {};

    for (int k0 = 0; k0 < DIN; k0 += 16) {
        // x tile: thread (k = tid%16, r = tid/16), rows stride 16
        {
            const int k = tid & 15;
            const int r = tid >> 4;
            #pragma unroll
            for (int i = 0; i < 4; i++)
                xs[k][r + 16 * i] = x[(size_t)(m0 + r + 16 * i) * DIN + (k0 + k)];
        }
        // W tile: thread (c = tid%64, kr = tid/64), k stride 4
        {
            const int c  = tid & 63;
            const int kr = tid >> 6;
            #pragma unroll
            for (int i = 0; i < 4; i++)
                ws[kr + 4 * i][c] = W[(size_t)(k0 + kr + 4 * i) * HID + (h0 + c)];
        }
        __syncthreads();

        #pragma unroll
        for (int kk = 0; kk < 16; kk++) {
            const float4 a4 = *(const float4*)&xs[kk][ty * 4];
            const float4 b4 = *(const float4*)&ws[kk][tx * 4];
            const float av[4] = {a4.x, a4.y, a4.z, a4.w};
            const float bv[4] = {b4.x, b4.y, b4.z, b4.w};
            #pragma unroll
            for (int a = 0; a < 4; a++)
                #pragma unroll
                for (int b = 0; b < 4; b++)
                    acc[a][b] += av[a] * bv[b];
        }
        __syncthreads();
    }

    #pragma unroll
    for (int a = 0; a < 4; a++) {
        const int row = m0 + ty * 4 + a;
        float4 o;
        o.x = acc[a][0] + bias[h0 + tx * 4 + 0];
        o.y = acc[a][1] + bias[h0 + tx * 4 + 1];
        o.z = acc[a][2] + bias[h0 + tx * 4 + 2];
        o.w = acc[a][3] + bias[h0 + tx * 4 + 3];
        *(float4*)&out[(size_t)row * HID + h0 + tx * 4] = o;
    }
}

// =================================================================
// Fused flash attention (no 1/sqrt(d) scaling, faithful to ref).
// Grid (SEQ/BQ = 32, BATCH = 4) = 128 blocks, 512 threads.
// BQ = 128 queries/block, BK = 64 keys/tile, online softmax.
// Q,K in smem d-major (transposed) for float4 inner loop;
// strides chosen so STS.128 transpose writes are bank-conflict-free
// (stride % 32-in-float4-banks pattern = 4d mod 32).
// =================================================================
#define BQ 128
#define BK 64
#define ATH 512
#define QS_STRIDE 132   // BQ + 4
#define KS_STRIDE 68    // BK + 4
#define PS_STRIDE 68    // BK + 4
#define LOG2E 1.4426950408889634f

#define SMEM_FLOATS (HID * QS_STRIDE + HID * KS_STRIDE + BK * HID + BQ * PS_STRIDE)

__global__ void __launch_bounds__(ATH, 1)
attn_kernel(const float* __restrict__ Q, const float* __restrict__ K,
            const float* __restrict__ V, float* __restrict__ out)
{
    extern __shared__ float sm[];
    float* Qs = sm;                        // [HID][QS_STRIDE]  (d-major, col = q row)
    float* Ks = Qs + HID * QS_STRIDE;      // [HID][KS_STRIDE]  (d-major, col = k row)
    float* Vs = Ks + HID * KS_STRIDE;      // [BK][HID]         (natural)
    float* Ps = Vs + BK * HID;             // [BQ][PS_STRIDE]

    const int tid = threadIdx.x;
    const int ty  = tid >> 4;              // 0..31  -> 4 query rows each
    const int tx  = tid & 15;              // 0..15  -> 4 key cols / 8 out cols each
    const int b   = blockIdx.y;
    const int q0  = blockIdx.x * BQ;

    const float* Qb = Q + (size_t)b * SEQ * HID;
    const float* Kb = K + (size_t)b * SEQ * HID;
    const float* Vb = V + (size_t)b * SEQ * HID;

    // ---- load Q tile transposed: Qs[d][r] ----
    {
        const int d  = tid & 127;
        const int r0 = (tid >> 7) * 4;     // 0,4,8,12
        #pragma unroll
        for (int base = 0; base < BQ; base += 16) {
            const int r = base + r0;
            float4 t;
            t.x = Qb[(size_t)(q0 + r + 0) * HID + d];
            t.y = Qb[(size_t)(q0 + r + 1) * HID + d];
            t.z = Qb[(size_t)(q0 + r + 2) * HID + d];
            t.w = Qb[(size_t)(q0 + r + 3) * HID + d];
            *(float4*)&Qs[d * QS_STRIDE + r] = t;
        }
    }

    float O[4][8] = {};
    float m_r[4], l_r[4];
    #pragma unroll
    for (int a = 0; a < 4; a++) { m_r[a] = -1e30f; l_r[a] = 0.f; }

    for (int k0 = 0; k0 < SEQ; k0 += BK) {
        __syncthreads();   // previous tile's PV reads of Vs/Ps done

        // ---- load K tile transposed + V tile natural ----
        {
            const int d  = tid & 127;
            const int r0 = (tid >> 7) * 4;
            #pragma unroll
            for (int base = 0; base < BK; base += 16) {
                const int r = base + r0;
                float4 t;
                t.x = Kb[(size_t)(k0 + r + 0) * HID + d];
                t.y = Kb[(size_t)(k0 + r + 1) * HID + d];
                t.z = Kb[(size_t)(k0 + r + 2) * HID + d];
                t.w = Kb[(size_t)(k0 + r + 3) * HID + d];
                *(float4*)&Ks[d * KS_STRIDE + r] = t;
            }
            const int c  = (tid & 31) * 4;
            const int j0 = tid >> 5;       // 0..15
            #pragma unroll
            for (int base = 0; base < BK; base += 16) {
                *(float4*)&Vs[(base + j0) * HID + c] =
                    *(const float4*)&Vb[(size_t)(k0 + base + j0) * HID + c];
            }
        }
        __syncthreads();

        // ---- S = Q K^T  (64x... per-thread 4x4 micro-tile) ----
        float s[4][4] = {};
        #pragma unroll 8
        for (int d = 0; d < HID; d++) {
            const float4 q4 = *(const float4*)&Qs[d * QS_STRIDE + ty * 4];
            const float4 k4 = *(const float4*)&Ks[d * KS_STRIDE + tx * 4];
            const float qv[4] = {q4.x, q4.y, q4.z, q4.w};
            const float kv[4] = {k4.x, k4.y, k4.z, k4.w};
            #pragma unroll
            for (int a = 0; a < 4; a++)
                #pragma unroll
                for (int bb = 0; bb < 4; bb++)
                    s[a][bb] += qv[a] * kv[bb];
        }

        // ---- online softmax (row spread over 16 tx threads) ----
        #pragma unroll
        for (int a = 0; a < 4; a++) {
            float mx = fmaxf(fmaxf(s[a][0], s[a][1]), fmaxf(s[a][2], s[a][3]));
            #pragma unroll
            for (int o = 8; o; o >>= 1)
                mx = fmaxf(mx, __shfl_xor_sync(0xFFFFFFFFu, mx, o, 16));
            const float mnew = fmaxf(m_r[a], mx);
            const float corr = exp2f((m_r[a] - mnew) * LOG2E);
            m_r[a] = mnew;
            float p[4], rs = 0.f;
            #pragma unroll
            for (int bb = 0; bb < 4; bb++) {
                p[bb] = exp2f((s[a][bb] - mnew) * LOG2E);
                rs += p[bb];
            }
            #pragma unroll
            for (int o = 8; o; o >>= 1)
                rs += __shfl_xor_sync(0xFFFFFFFFu, rs, o, 16);
            l_r[a] = l_r[a] * corr + rs;
            #pragma unroll
            for (int c = 0; c < 8; c++) O[a][c] *= corr;
            *(float4*)&Ps[(ty * 4 + a) * PS_STRIDE + tx * 4] =
                make_float4(p[0], p[1], p[2], p[3]);
        }
        __syncthreads();   // Ps visible to all

        // ---- O += P * V ----
        #pragma unroll 4
        for (int j = 0; j < BK; j++) {
            const float4 v0 = *(const float4*)&Vs[j * HID + tx * 8];
            const float4 v1 = *(const float4*)&Vs[j * HID + tx * 8 + 4];
            #pragma unroll
            for (int a = 0; a < 4; a++) {
                const float pa = Ps[(ty * 4 + a) * PS_STRIDE + j];
                O[a][0] += pa * v0.x;  O[a][1] += pa * v0.y;
                O[a][2] += pa * v0.z;  O[a][3] += pa * v0.w;
                O[a][4] += pa * v1.x;  O[a][5] += pa * v1.y;
                O[a][6] += pa * v1.z;  O[a][7] += pa * v1.w;
            }
        }
    }

    // ---- epilogue: out = O / l ----
    #pragma unroll
    for (int a = 0; a < 4; a++) {
        const float inv = 1.0f / l_r[a];
        const int row = q0 + ty * 4 + a;
        float* op = out + ((size_t)b * SEQ + row) * HID + tx * 8;
        float4 o0, o1;
        o0.x = O[a][0] * inv; o0.y = O[a][1] * inv;
        o0.z = O[a][2] * inv; o0.w = O[a][3] * inv;
        o1.x = O[a][4] * inv; o1.y = O[a][5] * inv;
        o1.z = O[a][6] * inv; o1.w = O[a][7] * inv;
        *(float4*)op       = o0;
        *(float4*)(op + 4) = o1;
    }
}

// =================================================================
// launch
// =================================================================
extern "C" void kernel_launch(void* const* d_in, const int* in_sizes, int n_in,
                              void* d_out, int out_size)
{
    (void)in_sizes; (void)n_in; (void)out_size;
    const float* x  = (const float*)d_in[0];
    const float* Wq = (const float*)d_in[1];
    const float* bq = (const float*)d_in[2];
    const float* Wk = (const float*)d_in[3];
    const float* bk = (const float*)d_in[4];
    const float* Wv = (const float*)d_in[5];
    const float* bv = (const float*)d_in[6];
    float* out = (float*)d_out;

    float *q, *k, *v;
    cudaGetSymbolAddress((void**)&q, g_q);
    cudaGetSymbolAddress((void**)&k, g_k);
    cudaGetSymbolAddress((void**)&v, g_v);

    const int smem_bytes = SMEM_FLOATS * (int)sizeof(float);  // 169,984 B
    cudaFuncSetAttribute(attn_kernel,
                         cudaFuncAttributeMaxDynamicSharedMemorySize, smem_bytes);

    dim3 pgrid((BATCH * SEQ) / 64, HID / 64);   // (256, 2)
    proj_kernel<<<pgrid, 256>>>(x, Wq, bq, q);
    proj_kernel<<<pgrid, 256>>>(x, Wk, bk, k);
    proj_kernel<<<pgrid, 256>>>(x, Wv, bv, v);

    dim3 agrid(SEQ / BQ, BATCH);                // (32, 4)
    attn_kernel<<<agrid, ATH, smem_bytes>>>(q, k, v, out);
}

// round 4
// speedup vs baseline: 1.0011x; 1.0008x over previous
#include <cuda_runtime.h>
#include <math.h>

#define BATCH 4
#define SEQ   4096
#define DIN   256
#define HID   128

// ---------------- scratch (no cudaMalloc allowed) ----------------
__device__ float g_q[BATCH * SEQ * HID];
__device__ float g_k[BATCH * SEQ * HID];
__device__ float g_v[BATCH * SEQ * HID];

// =================================================================
// QKV projection: out[m][h] = sum_k x[m][k] * W[k][h] + b[h]
// M = BATCH*SEQ = 16384, K = 256, H = 128.
// Block 256 threads (16x16), tile 64x64, TK = 16.
// =================================================================
__global__ void __launch_bounds__(256)
proj_kernel(const float* __restrict__ x, const float* __restrict__ W,
            const float* __restrict__ bias, float* __restrict__ out)
{
    __shared__ float xs[16][68];   // [k][m] transposed
    __shared__ float ws[16][68];   // [k][h]

    const int tid = threadIdx.x;
    const int ty  = tid >> 4;      // 0..15 (row group)
    const int tx  = tid & 15;      // 0..15 (col group)
    const int m0  = blockIdx.x * 64;
    const int h0  = blockIdx.y * 64;

    float acc[4][4] = {};

    for (int k0 = 0; k0 < DIN; k0 += 16) {
        // x tile: thread (k = tid%16, r = tid/16), rows stride 16
        {
            const int k = tid & 15;
            const int r = tid >> 4;
            #pragma unroll
            for (int i = 0; i < 4; i++)
                xs[k][r + 16 * i] = x[(size_t)(m0 + r + 16 * i) * DIN + (k0 + k)];
        }
        // W tile: thread (c = tid%64, kr = tid/64), k stride 4
        {
            const int c  = tid & 63;
            const int kr = tid >> 6;
            #pragma unroll
            for (int i = 0; i < 4; i++)
                ws[kr + 4 * i][c] = W[(size_t)(k0 + kr + 4 * i) * HID + (h0 + c)];
        }
        __syncthreads();

        #pragma unroll
        for (int kk = 0; kk < 16; kk++) {
            const float4 a4 = *(const float4*)&xs[kk][ty * 4];
            const float4 b4 = *(const float4*)&ws[kk][tx * 4];
            const float av[4] = {a4.x, a4.y, a4.z, a4.w};
            const float bv[4] = {b4.x, b4.y, b4.z, b4.w};
            #pragma unroll
            for (int a = 0; a < 4; a++)
                #pragma unroll
                for (int b = 0; b < 4; b++)
                    acc[a][b] += av[a] * bv[b];
        }
        __syncthreads();
    }

    #pragma unroll
    for (int a = 0; a < 4; a++) {
        const int row = m0 + ty * 4 + a;
        float4 o;
        o.x = acc[a][0] + bias[h0 + tx * 4 + 0];
        o.y = acc[a][1] + bias[h0 + tx * 4 + 1];
        o.z = acc[a][2] + bias[h0 + tx * 4 + 2];
        o.w = acc[a][3] + bias[h0 + tx * 4 + 3];
        *(float4*)&out[(size_t)row * HID + h0 + tx * 4] = o;
    }
}

// =================================================================
// Fused flash attention (no 1/sqrt(d) scaling, faithful to ref).
// Grid (SEQ/BQ = 32, BATCH = 4) = 128 blocks, 512 threads.
// BQ = 128 queries/block, BK = 64 keys/tile, online softmax.
// Q,K in smem d-major (transposed) for float4 inner loop;
// strides chosen so STS.128 transpose writes are bank-conflict-free
// (stride % 32-in-float4-banks pattern = 4d mod 32).
// =================================================================
#define BQ 128
#define BK 64
#define ATH 512
#define QS_STRIDE 132   // BQ + 4
#define KS_STRIDE 68    // BK + 4
#define PS_STRIDE 68    // BK + 4
#define LOG2E 1.4426950408889634f

#define SMEM_FLOATS (HID * QS_STRIDE + HID * KS_STRIDE + BK * HID + BQ * PS_STRIDE)

__global__ void __launch_bounds__(ATH, 1)
attn_kernel(const float* __restrict__ Q, const float* __restrict__ K,
            const float* __restrict__ V, float* __restrict__ out)
{
    extern __shared__ float sm[];
    float* Qs = sm;                        // [HID][QS_STRIDE]  (d-major, col = q row)
    float* Ks = Qs + HID * QS_STRIDE;      // [HID][KS_STRIDE]  (d-major, col = k row)
    float* Vs = Ks + HID * KS_STRIDE;      // [BK][HID]         (natural)
    float* Ps = Vs + BK * HID;             // [BQ][PS_STRIDE]

    const int tid = threadIdx.x;
    const int ty  = tid >> 4;              // 0..31  -> 4 query rows each
    const int tx  = tid & 15;              // 0..15  -> 4 key cols / 8 out cols each
    const int b   = blockIdx.y;
    const int q0  = blockIdx.x * BQ;

    const float* Qb = Q + (size_t)b * SEQ * HID;
    const float* Kb = K + (size_t)b * SEQ * HID;
    const float* Vb = V + (size_t)b * SEQ * HID;

    // ---- load Q tile transposed: Qs[d][r] ----
    {
        const int d  = tid & 127;
        const int r0 = (tid >> 7) * 4;     // 0,4,8,12
        #pragma unroll
        for (int base = 0; base < BQ; base += 16) {
            const int r = base + r0;
            float4 t;
            t.x = Qb[(size_t)(q0 + r + 0) * HID + d];
            t.y = Qb[(size_t)(q0 + r + 1) * HID + d];
            t.z = Qb[(size_t)(q0 + r + 2) * HID + d];
            t.w = Qb[(size_t)(q0 + r + 3) * HID + d];
            *(float4*)&Qs[d * QS_STRIDE + r] = t;
        }
    }

    float O[4][8] = {};
    float m_r[4], l_r[4];
    #pragma unroll
    for (int a = 0; a < 4; a++) { m_r[a] = -1e30f; l_r[a] = 0.f; }

    for (int k0 = 0; k0 < SEQ; k0 += BK) {
        __syncthreads();   // previous tile's PV reads of Vs/Ps done

        // ---- load K tile transposed + V tile natural ----
        {
            const int d  = tid & 127;
            const int r0 = (tid >> 7) * 4;
            #pragma unroll
            for (int base = 0; base < BK; base += 16) {
                const int r = base + r0;
                float4 t;
                t.x = Kb[(size_t)(k0 + r + 0) * HID + d];
                t.y = Kb[(size_t)(k0 + r + 1) * HID + d];
                t.z = Kb[(size_t)(k0 + r + 2) * HID + d];
                t.w = Kb[(size_t)(k0 + r + 3) * HID + d];
                *(float4*)&Ks[d * KS_STRIDE + r] = t;
            }
            const int c  = (tid & 31) * 4;
            const int j0 = tid >> 5;       // 0..15
            #pragma unroll
            for (int base = 0; base < BK; base += 16) {
                *(float4*)&Vs[(base + j0) * HID + c] =
                    *(const float4*)&Vb[(size_t)(k0 + base + j0) * HID + c];
            }
        }
        __syncthreads();

        // ---- S = Q K^T  (64x... per-thread 4x4 micro-tile) ----
        float s[4][4] = {};
        #pragma unroll 8
        for (int d = 0; d < HID; d++) {
            const float4 q4 = *(const float4*)&Qs[d * QS_STRIDE + ty * 4];
            const float4 k4 = *(const float4*)&Ks[d * KS_STRIDE + tx * 4];
            const float qv[4] = {q4.x, q4.y, q4.z, q4.w};
            const float kv[4] = {k4.x, k4.y, k4.z, k4.w};
            #pragma unroll
            for (int a = 0; a < 4; a++)
                #pragma unroll
                for (int bb = 0; bb < 4; bb++)
                    s[a][bb] += qv[a] * kv[bb];
        }

        // ---- online softmax (row spread over 16 tx threads) ----
        #pragma unroll
        for (int a = 0; a < 4; a++) {
            float mx = fmaxf(fmaxf(s[a][0], s[a][1]), fmaxf(s[a][2], s[a][3]));
            #pragma unroll
            for (int o = 8; o; o >>= 1)
                mx = fmaxf(mx, __shfl_xor_sync(0xFFFFFFFFu, mx, o, 16));
            const float mnew = fmaxf(m_r[a], mx);
            const float corr = exp2f((m_r[a] - mnew) * LOG2E);
            m_r[a] = mnew;
            float p[4], rs = 0.f;
            #pragma unroll
            for (int bb = 0; bb < 4; bb++) {
                p[bb] = exp2f((s[a][bb] - mnew) * LOG2E);
                rs += p[bb];
            }
            #pragma unroll
            for (int o = 8; o; o >>= 1)
                rs += __shfl_xor_sync(0xFFFFFFFFu, rs, o, 16);
            l_r[a] = l_r[a] * corr + rs;
            #pragma unroll
            for (int c = 0; c < 8; c++) O[a][c] *= corr;
            *(float4*)&Ps[(ty * 4 + a) * PS_STRIDE + tx * 4] =
                make_float4(p[0], p[1], p[2], p[3]);
        }
        __syncthreads();   // Ps visible to all

        // ---- O += P * V ----
        #pragma unroll 4
        for (int j = 0; j < BK; j++) {
            const float4 v0 = *(const float4*)&Vs[j * HID + tx * 8];
            const float4 v1 = *(const float4*)&Vs[j * HID + tx * 8 + 4];
            #pragma unroll
            for (int a = 0; a < 4; a++) {
                const float pa = Ps[(ty * 4 + a) * PS_STRIDE + j];
                O[a][0] += pa * v0.x;  O[a][1] += pa * v0.y;
                O[a][2] += pa * v0.z;  O[a][3] += pa * v0.w;
                O[a][4] += pa * v1.x;  O[a][5] += pa * v1.y;
                O[a][6] += pa * v1.z;  O[a][7] += pa * v1.w;
            }
        }
    }

    // ---- epilogue: out = O / l ----
    #pragma unroll
    for (int a = 0; a < 4; a++) {
        const float inv = 1.0f / l_r[a];
        const int row = q0 + ty * 4 + a;
        float* op = out + ((size_t)b * SEQ + row) * HID + tx * 8;
        float4 o0, o1;
        o0.x = O[a][0] * inv; o0.y = O[a][1] * inv;
        o0.z = O[a][2] * inv; o0.w = O[a][3] * inv;
        o1.x = O[a][4] * inv; o1.y = O[a][5] * inv;
        o1.z = O[a][6] * inv; o1.w = O[a][7] * inv;
        *(float4*)op       = o0;
        *(float4*)(op + 4) = o1;
    }
}

// =================================================================
// launch
// =================================================================
extern "C" void kernel_launch(void* const* d_in, const int* in_sizes, int n_in,
                              void* d_out, int out_size)
{
    (void)in_sizes; (void)n_in; (void)out_size;
    const float* x  = (const float*)d_in[0];
    const float* Wq = (const float*)d_in[1];
    const float* bq = (const float*)d_in[2];
    const float* Wk = (const float*)d_in[3];
    const float* bk = (const float*)d_in[4];
    const float* Wv = (const float*)d_in[5];
    const float* bv = (const float*)d_in[6];
    float* out = (float*)d_out;

    float *q, *k, *v;
    cudaGetSymbolAddress((void**)&q, g_q);
    cudaGetSymbolAddress((void**)&k, g_k);
    cudaGetSymbolAddress((void**)&v, g_v);

    const int smem_bytes = SMEM_FLOATS * (int)sizeof(float);  // 169,984 B
    cudaFuncSetAttribute(attn_kernel,
                         cudaFuncAttributeMaxDynamicSharedMemorySize, smem_bytes);

    dim3 pgrid((BATCH * SEQ) / 64, HID / 64);   // (256, 2)
    proj_kernel<<<pgrid, 256>>>(x, Wq, bq, q);
    proj_kernel<<<pgrid, 256>>>(x, Wk, bk, k);
    proj_kernel<<<pgrid, 256>>>(x, Wv, bv, v);

    dim3 agrid(SEQ / BQ, BATCH);                // (32, 4)
    attn_kernel<<<agrid, ATH, smem_bytes>>>(q, k, v, out);
}